// round 1
// baseline (speedup 1.0000x reference)
#include <cuda_runtime.h>

// Problem constants
#define B_TOTAL 4096
#define D_DIM   200
#define U_DIM   32
#define T_DIM   4
#define A_DIM   20
#define N_NEI   10

// Launch config
#define SUBS    8                 // batch elements processed per block iteration
#define THREADS (SUBS * 128)      // 1024 threads: 128 per sub (4 warps = 4 types)
#define GRID    148

// Shared memory layout (float offsets)
#define OFF_WS  0
#define SZ_WS   (T_DIM * U_DIM * D_DIM)   // 25600  trans_weights
#define OFF_S1  (OFF_WS + SZ_WS)
#define SZ_S1   (T_DIM * U_DIM * A_DIM)   // 2560   trans_weights_s1
#define OFF_S2  (OFF_S1 + SZ_S1)
#define SZ_S2   (T_DIM * A_DIM)           // 80     trans_weights_s2 (last dim 1 squeezed)
#define OFF_NTE (OFF_S2 + SZ_S2)
#define SZ_NTE  (SUBS * T_DIM * U_DIM)    // 1024   per-sub node_type_embed
#define OFF_LG  (OFF_NTE + SZ_NTE)
#define SZ_LG   (SUBS * T_DIM)            // 32     logits
#define OFF_AG  (OFF_LG + SZ_LG)
#define SZ_AG   (SUBS * U_DIM)            // 256    agg vectors
#define OFF_NP  (OFF_AG + SZ_AG)
#define SZ_NP   (SUBS * 4)                // 32     norm partials (4 warps per sub)
#define SMEM_FLOATS (OFF_NP + SZ_NP)      // 29584 floats = 118336 bytes

__global__ __launch_bounds__(THREADS, 1)
void gatne_kernel(const int*   __restrict__ train_inputs,
                  const int*   __restrict__ train_types,
                  const int*   __restrict__ node_neigh,
                  const float* __restrict__ node_emb,     // [NUM_NODES, 200]
                  const float* __restrict__ nte_g,        // [NUM_NODES, 4, 32]
                  const float* __restrict__ w_g,          // [4, 32, 200]
                  const float* __restrict__ s1_g,         // [4, 32, 20]
                  const float* __restrict__ s2_g,         // [4, 20, 1]
                  float*       __restrict__ out)          // [B, 200]
{
    extern __shared__ float sm[];
    const int tid = threadIdx.x;

    // ---- Stage all weights into shared memory (once per block) ----
    for (int i = tid; i < SZ_WS; i += THREADS) sm[OFF_WS + i] = w_g[i];
    for (int i = tid; i < SZ_S1; i += THREADS) sm[OFF_S1 + i] = s1_g[i];
    for (int i = tid; i < SZ_S2; i += THREADS) sm[OFF_S2 + i] = s2_g[i];
    __syncthreads();

    const int sub  = tid >> 7;       // 0..7
    const int wg   = tid & 127;      // thread within sub
    const int t    = wg >> 5;        // 0..3 (type handled by this warp)
    const int lane = wg & 31;

    const int stride = gridDim.x * SUBS;                    // 1184
    const int nIter  = (B_TOTAL + stride - 1) / stride;     // 4

    for (int it = 0; it < nIter; it++) {
        const int b = blockIdx.x * SUBS + sub + it * stride;
        const bool active = (b < B_TOTAL);

        // ---- Phase A: neighbor gather + sum (warp t sums type t) ----
        if (active) {
            const int* nb = node_neigh + (long)b * (T_DIM * N_NEI) + t * N_NEI;
            int idx[N_NEI];
#pragma unroll
            for (int n = 0; n < N_NEI; n++) idx[n] = nb[n];
            float acc = 0.0f;
#pragma unroll
            for (int n = 0; n < N_NEI; n++)
                acc += nte_g[(long)idx[n] * (T_DIM * U_DIM) + t * U_DIM + lane];
            sm[OFF_NTE + (sub * T_DIM + t) * U_DIM + lane] = acc;
        }
        __syncthreads();

        // ---- Phase B: logits (each warp its own t) ----
        int tt = 0;
        if (active) {
            tt = train_types[b];
            float hpart = 0.0f;
            if (lane < A_DIM) {
                float dot = 0.0f;
#pragma unroll
                for (int u = 0; u < U_DIM; u++)
                    dot += sm[OFF_NTE + (sub * T_DIM + t) * U_DIM + u]
                         * sm[OFF_S1 + (tt * U_DIM + u) * A_DIM + lane];
                hpart = tanhf(dot) * sm[OFF_S2 + tt * A_DIM + lane];
            }
#pragma unroll
            for (int o = 16; o; o >>= 1)
                hpart += __shfl_down_sync(0xffffffffu, hpart, o);
            if (lane == 0) sm[OFF_LG + sub * T_DIM + t] = hpart;
        }
        __syncthreads();

        // ---- Softmax + agg (warp 0 of each sub) ----
        if (active && t == 0) {
            float l0 = sm[OFF_LG + sub * 4 + 0];
            float l1 = sm[OFF_LG + sub * 4 + 1];
            float l2 = sm[OFF_LG + sub * 4 + 2];
            float l3 = sm[OFF_LG + sub * 4 + 3];
            float m  = fmaxf(fmaxf(l0, l1), fmaxf(l2, l3));
            float e0 = expf(l0 - m), e1 = expf(l1 - m);
            float e2 = expf(l2 - m), e3 = expf(l3 - m);
            float inv = 1.0f / (e0 + e1 + e2 + e3);
            float a0 = e0 * inv, a1 = e1 * inv, a2 = e2 * inv, a3 = e3 * inv;
            float agg = a0 * sm[OFF_NTE + (sub * 4 + 0) * U_DIM + lane]
                      + a1 * sm[OFF_NTE + (sub * 4 + 1) * U_DIM + lane]
                      + a2 * sm[OFF_NTE + (sub * 4 + 2) * U_DIM + lane]
                      + a3 * sm[OFF_NTE + (sub * 4 + 3) * U_DIM + lane];
            sm[OFF_AG + sub * U_DIM + lane] = agg;
        }
        __syncthreads();

        // ---- Phase C: out[d] = node_embed[d] + agg . W[tt,:,d], then L2-normalize ----
        float out0 = 0.0f, out1 = 0.0f;
        if (active) {
            float ag[U_DIM];
#pragma unroll
            for (int u = 0; u < U_DIM; u++) ag[u] = sm[OFF_AG + sub * U_DIM + u];

            const long  inp  = (long)train_inputs[b];
            const float* wrow = sm + OFF_WS + tt * (U_DIM * D_DIM);

            {
                const int d0 = wg;                     // 0..127
                float acc0 = node_emb[inp * D_DIM + d0];
#pragma unroll
                for (int u = 0; u < U_DIM; u++)
                    acc0 += ag[u] * wrow[u * D_DIM + d0];
                out0 = acc0;
            }
            if (wg < D_DIM - 128) {                    // d1 = 128..199
                const int d1 = wg + 128;
                float acc1 = node_emb[inp * D_DIM + d1];
#pragma unroll
                for (int u = 0; u < U_DIM; u++)
                    acc1 += ag[u] * wrow[u * D_DIM + d1];
                out1 = acc1;
            }
        }

        // norm reduction across the 128 threads of this sub
        float ss = out0 * out0 + out1 * out1;
#pragma unroll
        for (int o = 16; o; o >>= 1)
            ss += __shfl_down_sync(0xffffffffu, ss, o);
        if (lane == 0) sm[OFF_NP + sub * 4 + t] = ss;
        __syncthreads();

        if (active) {
            const float total = sm[OFF_NP + sub * 4 + 0] + sm[OFF_NP + sub * 4 + 1]
                              + sm[OFF_NP + sub * 4 + 2] + sm[OFF_NP + sub * 4 + 3];
            const float scale = 1.0f / fmaxf(sqrtf(total), 1e-12f);
            out[(long)b * D_DIM + wg] = out0 * scale;
            if (wg < D_DIM - 128)
                out[(long)b * D_DIM + wg + 128] = out1 * scale;
        }
        __syncthreads();   // protect smem reuse next iteration
    }
}

extern "C" void kernel_launch(void* const* d_in, const int* in_sizes, int n_in,
                              void* d_out, int out_size)
{
    const int*   train_inputs = (const int*)  d_in[0];
    const int*   train_types  = (const int*)  d_in[1];
    const int*   node_neigh   = (const int*)  d_in[2];
    const float* node_emb     = (const float*)d_in[3];
    const float* nte          = (const float*)d_in[4];
    const float* w            = (const float*)d_in[5];
    const float* s1           = (const float*)d_in[6];
    const float* s2           = (const float*)d_in[7];
    float*       out          = (float*)d_out;

    const int smem_bytes = SMEM_FLOATS * (int)sizeof(float);  // 118336
    cudaFuncSetAttribute(gatne_kernel,
                         cudaFuncAttributeMaxDynamicSharedMemorySize, smem_bytes);

    gatne_kernel<<<GRID, THREADS, smem_bytes>>>(
        train_inputs, train_types, node_neigh,
        node_emb, nte, w, s1, s2, out);
}

// round 7
// speedup vs baseline: 1.3617x; 1.3617x over previous
#include <cuda_runtime.h>

// Problem constants
#define B_TOTAL 4096
#define D_DIM   200
#define U_DIM   32
#define T_DIM   4
#define A_DIM   20
#define N_NEI   10

#define THREADS 1024
#define GRID    148

// Shared memory: weights only (no cross-warp scratch needed)
#define SZ_WS   (T_DIM * U_DIM * D_DIM)   // 25600 floats
#define SZ_S1   (T_DIM * U_DIM * A_DIM)   // 2560
#define SZ_S2   (T_DIM * A_DIM)           // 80
#define SMEM_FLOATS (SZ_WS + SZ_S1 + SZ_S2)  // 28240 floats = 112,960 B

__global__ __launch_bounds__(THREADS, 1)
void gatne_kernel(const int*   __restrict__ train_inputs,
                  const int*   __restrict__ train_types,
                  const int*   __restrict__ node_neigh,   // [B,4,10]
                  const float* __restrict__ node_emb,     // [NUM_NODES,200]
                  const float* __restrict__ nte_g,        // [NUM_NODES,4,32]
                  const float* __restrict__ w_g,          // [4,32,200]
                  const float* __restrict__ s1_g,         // [4,32,20]
                  const float* __restrict__ s2_g,         // [4,20,1]
                  float*       __restrict__ out)          // [B,200]
{
    extern __shared__ float sm[];
    float* Wsm  = sm;
    float* S1sm = sm + SZ_WS;
    float* S2sm = S1sm + SZ_S1;

    const int tid  = threadIdx.x;
    const int warp = tid >> 5;
    const int lane = tid & 31;

    // One warp per batch element, spread for load balance across blocks
    const int b = warp * GRID + blockIdx.x;     // 0..4735
    const bool active = (b < B_TOTAL);

    // ---- Issue per-warp scalar loads first (latency covered by staging) ----
    int  tt  = 0;
    long inp = 0;
    if (active) {
        tt  = train_types[b];
        inp = (long)train_inputs[b];
    }

    // ---- Stage all weights into shared memory (vectorized, once per block) ----
    {
        const float4* wsrc  = (const float4*)w_g;
        float4*       wdst  = (float4*)Wsm;
        for (int i = tid; i < SZ_WS / 4; i += THREADS) wdst[i] = wsrc[i];
        const float4* s1src = (const float4*)s1_g;
        float4*       s1dst = (float4*)S1sm;
        for (int i = tid; i < SZ_S1 / 4; i += THREADS) s1dst[i] = s1src[i];
        if (tid < SZ_S2) S2sm[tid] = s2_g[tid];
    }

    // ---- Phase A (pre-sync: touches no smem): neighbor gather + sum.
    //      lane = u dimension (perfect 128B rows). Overlaps the staging barrier.
    float acc[T_DIM];
    if (active) {
        int nidx[T_DIM * N_NEI];
        const int4* nb4 = (const int4*)(node_neigh + (long)b * (T_DIM * N_NEI));
#pragma unroll
        for (int i = 0; i < (T_DIM * N_NEI) / 4; i++) {
            int4 v = nb4[i];
            nidx[4 * i + 0] = v.x; nidx[4 * i + 1] = v.y;
            nidx[4 * i + 2] = v.z; nidx[4 * i + 3] = v.w;
        }
#pragma unroll
        for (int t = 0; t < T_DIM; t++) {
            float a = 0.0f;
#pragma unroll
            for (int n = 0; n < N_NEI; n++)
                a += nte_g[(long)nidx[t * N_NEI + n] * (T_DIM * U_DIM) + t * U_DIM + lane];
            acc[t] = a;
        }
    }

    __syncthreads();   // only block-wide sync in the kernel
    if (!active) return;

    // ---- Phase B: logits. lane = a dimension (a < 20); nte transposed via shuffles ----
    float s1c[U_DIM];
#pragma unroll
    for (int u = 0; u < U_DIM; u++)
        s1c[u] = (lane < A_DIM) ? S1sm[(tt * U_DIM + u) * A_DIM + lane] : 0.0f;
    const float s2v = (lane < A_DIM) ? S2sm[tt * A_DIM + lane] : 0.0f;

    float logit[T_DIM];
#pragma unroll
    for (int t = 0; t < T_DIM; t++) {
        float dot = 0.0f;
#pragma unroll
        for (int u = 0; u < U_DIM; u++) {
            float v = __shfl_sync(0xffffffffu, acc[t], u);
            dot += v * s1c[u];
        }
        float hp = (lane < A_DIM) ? tanhf(dot) * s2v : 0.0f;
#pragma unroll
        for (int o = 16; o; o >>= 1)
            hp += __shfl_xor_sync(0xffffffffu, hp, o);
        logit[t] = hp;   // identical on all lanes
    }

    // ---- Softmax (registers, redundant per lane) + agg (lane = u) ----
    float m  = fmaxf(fmaxf(logit[0], logit[1]), fmaxf(logit[2], logit[3]));
    float e0 = __expf(logit[0] - m), e1 = __expf(logit[1] - m);
    float e2 = __expf(logit[2] - m), e3 = __expf(logit[3] - m);
    float inv = 1.0f / (e0 + e1 + e2 + e3);
    float agg = (e0 * acc[0] + e1 * acc[1] + e2 * acc[2] + e3 * acc[3]) * inv;

    // ---- Phase C: out[d] = node_emb[d] + sum_u agg[u]*W[tt][u][d] (float2 over d) ----
    const float2* nep = (const float2*)(node_emb + inp * D_DIM);
    float2 o[4];
#pragma unroll
    for (int j = 0; j < 3; j++) o[j] = nep[lane + j * 32];
    o[3] = (lane < 4) ? nep[96 + lane] : make_float2(0.0f, 0.0f);

    const float* wbase = Wsm + tt * (U_DIM * D_DIM);
#pragma unroll
    for (int u = 0; u < U_DIM; u++) {
        float a = __shfl_sync(0xffffffffu, agg, u);
        const float2* wr = (const float2*)(wbase + u * D_DIM);
#pragma unroll
        for (int j = 0; j < 3; j++) {
            float2 w = wr[lane + j * 32];
            o[j].x += a * w.x;  o[j].y += a * w.y;
        }
        if (lane < 4) {
            float2 w = wr[96 + lane];
            o[3].x += a * w.x;  o[3].y += a * w.y;
        }
    }

    // ---- L2 norm across the warp, then scaled store ----
    float ss = o[0].x * o[0].x + o[0].y * o[0].y
             + o[1].x * o[1].x + o[1].y * o[1].y
             + o[2].x * o[2].x + o[2].y * o[2].y
             + o[3].x * o[3].x + o[3].y * o[3].y;
#pragma unroll
    for (int off = 16; off; off >>= 1)
        ss += __shfl_xor_sync(0xffffffffu, ss, off);
    const float scale = 1.0f / fmaxf(sqrtf(ss), 1e-12f);

    float2* op = (float2*)(out + (long)b * D_DIM);
#pragma unroll
    for (int j = 0; j < 3; j++) {
        float2 v = o[j];
        v.x *= scale; v.y *= scale;
        op[lane + j * 32] = v;
    }
    if (lane < 4) {
        float2 v = o[3];
        v.x *= scale; v.y *= scale;
        op[96 + lane] = v;
    }
}

extern "C" void kernel_launch(void* const* d_in, const int* in_sizes, int n_in,
                              void* d_out, int out_size)
{
    const int*   train_inputs = (const int*)  d_in[0];
    const int*   train_types  = (const int*)  d_in[1];
    const int*   node_neigh   = (const int*)  d_in[2];
    const float* node_emb     = (const float*)d_in[3];
    const float* nte          = (const float*)d_in[4];
    const float* w            = (const float*)d_in[5];
    const float* s1           = (const float*)d_in[6];
    const float* s2           = (const float*)d_in[7];
    float*       out          = (float*)d_out;

    const int smem_bytes = SMEM_FLOATS * (int)sizeof(float);  // 112,960
    cudaFuncSetAttribute(gatne_kernel,
                         cudaFuncAttributeMaxDynamicSharedMemorySize, smem_bytes);

    gatne_kernel<<<GRID, THREADS, smem_bytes>>>(
        train_inputs, train_types, node_neigh,
        node_emb, nte, w, s1, s2, out);
}

// round 10
// speedup vs baseline: 1.5496x; 1.1379x over previous
#include <cuda_runtime.h>

// Problem constants
#define B_TOTAL 4096
#define D_DIM   200
#define U_DIM   32
#define T_DIM   4
#define A_DIM   20
#define N_NEI   10

#define THREADS 1024
#define GRID    148
#define NWARPS  (THREADS / 32)

#define S1T_STRIDE 36                          // padded from 32: kills 20-way bank conflict

// Shared memory layout (float offsets)
#define OFF_WS   0
#define SZ_WS    (T_DIM * U_DIM * D_DIM)       // 25600  trans_weights
#define OFF_S1T  (OFF_WS + SZ_WS)
#define SZ_S1T   (T_DIM * A_DIM * S1T_STRIDE)  // 2880   s1 transposed+padded: [t][a][u(36)]
#define OFF_S2   (OFF_S1T + SZ_S1T)
#define SZ_S2    (T_DIM * A_DIM)               // 80
#define OFF_SCR  (OFF_S2 + SZ_S2)
#define SZ_SCR   (NWARPS * T_DIM * U_DIM)      // 4096   per-warp acc scratch [warp][t][u]
#define SMEM_FLOATS (OFF_SCR + SZ_SCR)         // 32656 floats = 130,624 B

__global__ __launch_bounds__(THREADS, 1)
void gatne_kernel(const int*   __restrict__ train_inputs,
                  const int*   __restrict__ train_types,
                  const int*   __restrict__ node_neigh,   // [B,4,10]
                  const float* __restrict__ node_emb,     // [NUM_NODES,200]
                  const float* __restrict__ nte_g,        // [NUM_NODES,4,32]
                  const float* __restrict__ w_g,          // [4,32,200]
                  const float* __restrict__ s1_g,         // [4,32,20]
                  const float* __restrict__ s2_g,         // [4,20,1]
                  float*       __restrict__ out)          // [B,200]
{
    extern __shared__ float sm[];
    float* Wsm   = sm + OFF_WS;
    float* S1Tsm = sm + OFF_S1T;
    float* S2sm  = sm + OFF_S2;
    float* SCR   = sm + OFF_SCR;

    const int tid  = threadIdx.x;
    const int warp = tid >> 5;
    const int lane = tid & 31;

    // One warp per batch element
    const int b = warp * GRID + blockIdx.x;     // 0..4735
    const bool active = (b < B_TOTAL);

    // ---- Per-warp scalar loads first (latency covered by staging) ----
    int  tt  = 0;
    long inp = 0;
    if (active) {
        tt  = train_types[b];
        inp = (long)train_inputs[b];
    }

    // ---- Stage weights into shared memory ----
    {
        const float4* wsrc = (const float4*)w_g;
        float4*       wdst = (float4*)Wsm;
        for (int i = tid; i < SZ_WS / 4; i += THREADS) wdst[i] = wsrc[i];
        // s1 transposed + padded: S1T[t][a][u] = s1_g[t][u][a]
        for (int i = tid; i < T_DIM * A_DIM * U_DIM; i += THREADS) {
            int t = i / (A_DIM * U_DIM);
            int r = i % (A_DIM * U_DIM);
            int a = r / U_DIM;
            int u = r % U_DIM;
            S1Tsm[(t * A_DIM + a) * S1T_STRIDE + u] = s1_g[(t * U_DIM + u) * A_DIM + a];
        }
        if (tid < SZ_S2) S2sm[tid] = s2_g[tid];
    }

    // ---- Phase A: gather. Lane group g (8 lanes) owns type g; each lane
    //      loads float4 (u = 4s..4s+3) of each 128B row. 10 LDG.128/lane. ----
    const int g = lane >> 3;        // type owned by this lane's group
    const int s = lane & 7;         // float4 slot within the row
    float4 acc4 = make_float4(0.f, 0.f, 0.f, 0.f);
    if (active) {
        const int* nb = node_neigh + (long)b * (T_DIM * N_NEI) + g * N_NEI;
        int idx[N_NEI];
#pragma unroll
        for (int i = 0; i < N_NEI; i++) idx[i] = nb[i];
#pragma unroll
        for (int i = 0; i < N_NEI; i++) {
            const float4 v = ((const float4*)nte_g)[(long)idx[i] * (T_DIM * U_DIM / 4) + g * 8 + s];
            acc4.x += v.x; acc4.y += v.y; acc4.z += v.z; acc4.w += v.w;
        }
        // scratch[warp][t=g][u=4s..4s+3]
        ((float4*)(SCR + warp * (T_DIM * U_DIM)))[g * 8 + s] = acc4;
    }

    __syncthreads();   // staging + scratch both visible
    if (!active) return;

    // ---- Phase B: logits. lane = a (a < 20). acc read via broadcast LDS.128,
    //      s1T read as float4 rows (padded stride -> max 3-way conflict). ----
    const float4* accS = (const float4*)(SCR + warp * (T_DIM * U_DIM));
    const float*  s1row = S1Tsm + (tt * A_DIM + (lane < A_DIM ? lane : 0)) * S1T_STRIDE;
    const float   s2v  = (lane < A_DIM) ? S2sm[tt * A_DIM + lane] : 0.0f;

    float dot[T_DIM] = {0.f, 0.f, 0.f, 0.f};
#pragma unroll
    for (int k = 0; k < 8; k++) {
        const float4 s1v = *(const float4*)(s1row + 4 * k);
#pragma unroll
        for (int t = 0; t < T_DIM; t++) {
            const float4 av = accS[t * 8 + k];
            dot[t] += av.x * s1v.x + av.y * s1v.y + av.z * s1v.z + av.w * s1v.w;
        }
    }

    float logit[T_DIM];
#pragma unroll
    for (int t = 0; t < T_DIM; t++) {
        float hp = (lane < A_DIM) ? tanhf(dot[t]) * s2v : 0.0f;
#pragma unroll
        for (int o = 16; o; o >>= 1)
            hp += __shfl_xor_sync(0xffffffffu, hp, o);
        logit[t] = hp;   // identical on all lanes
    }

    // ---- Softmax (registers, redundant per lane) ----
    const float m  = fmaxf(fmaxf(logit[0], logit[1]), fmaxf(logit[2], logit[3]));
    const float e0 = __expf(logit[0] - m), e1 = __expf(logit[1] - m);
    const float e2 = __expf(logit[2] - m), e3 = __expf(logit[3] - m);
    const float inv = 1.0f / (e0 + e1 + e2 + e3);

    // agg for u = lane: 4 conflict-free LDS.32 from scratch
    const float* scrW = SCR + warp * (T_DIM * U_DIM);
    const float agg = (e0 * scrW[0 * U_DIM + lane] + e1 * scrW[1 * U_DIM + lane]
                     + e2 * scrW[2 * U_DIM + lane] + e3 * scrW[3 * U_DIM + lane]) * inv;

    // ---- Phase C: out[d] = node_emb[d] + sum_u agg[u]*W[tt][u][d] (float2 over d) ----
    const float2* nep = (const float2*)(node_emb + inp * D_DIM);
    float2 o[4];
#pragma unroll
    for (int j = 0; j < 3; j++) o[j] = nep[lane + j * 32];
    o[3] = (lane < 4) ? nep[96 + lane] : make_float2(0.0f, 0.0f);

    const float* wbase = Wsm + tt * (U_DIM * D_DIM);
#pragma unroll
    for (int u = 0; u < U_DIM; u++) {
        const float a = __shfl_sync(0xffffffffu, agg, u);
        const float2* wr = (const float2*)(wbase + u * D_DIM);
#pragma unroll
        for (int j = 0; j < 3; j++) {
            const float2 w = wr[lane + j * 32];
            o[j].x += a * w.x;  o[j].y += a * w.y;
        }
        if (lane < 4) {
            const float2 w = wr[96 + lane];
            o[3].x += a * w.x;  o[3].y += a * w.y;
        }
    }

    // ---- L2 norm across the warp, then scaled store ----
    float ss = o[0].x * o[0].x + o[0].y * o[0].y
             + o[1].x * o[1].x + o[1].y * o[1].y
             + o[2].x * o[2].x + o[2].y * o[2].y
             + o[3].x * o[3].x + o[3].y * o[3].y;
#pragma unroll
    for (int off = 16; off; off >>= 1)
        ss += __shfl_xor_sync(0xffffffffu, ss, off);
    const float scale = 1.0f / fmaxf(sqrtf(ss), 1e-12f);

    float2* op = (float2*)(out + (long)b * D_DIM);
#pragma unroll
    for (int j = 0; j < 3; j++) {
        float2 v = o[j];
        v.x *= scale; v.y *= scale;
        op[lane + j * 32] = v;
    }
    if (lane < 4) {
        float2 v = o[3];
        v.x *= scale; v.y *= scale;
        op[96 + lane] = v;
    }
}

extern "C" void kernel_launch(void* const* d_in, const int* in_sizes, int n_in,
                              void* d_out, int out_size)
{
    const int*   train_inputs = (const int*)  d_in[0];
    const int*   train_types  = (const int*)  d_in[1];
    const int*   node_neigh   = (const int*)  d_in[2];
    const float* node_emb     = (const float*)d_in[3];
    const float* nte          = (const float*)d_in[4];
    const float* w            = (const float*)d_in[5];
    const float* s1           = (const float*)d_in[6];
    const float* s2           = (const float*)d_in[7];
    float*       out          = (float*)d_out;

    const int smem_bytes = SMEM_FLOATS * (int)sizeof(float);  // 130,624
    cudaFuncSetAttribute(gatne_kernel,
                         cudaFuncAttributeMaxDynamicSharedMemorySize, smem_bytes);

    gatne_kernel<<<GRID, THREADS, smem_bytes>>>(
        train_inputs, train_types, node_neigh,
        node_emb, nte, w, s1, s2, out);
}